// round 17
// baseline (speedup 1.0000x reference)
#include <cuda_runtime.h>
#include <mma.h>
#include <cuda_fp16.h>
#include <cstdint>

using namespace nvcuda;

#define Nn 2048
#define Dd 128
#define Cc 512
#define Kp 1024
#define TINV 14.285714285714286f
#define APADH 40
#define BPADH 136
#define GPAD 136
#define NB 296
#define NT 256
#define SMEM_BYTES 45568

// ----------------- scratch (device globals; allocation-free) -----------------
__device__ float    g_fes[Nn*Dd], g_fet[Nn*Dd];
__device__ __align__(16) __half g_fesh[Nn*Dd], g_feth[Nn*Dd];
__device__ unsigned g_Abits[Nn*64];
__device__ float    g_dinv[Nn];
__device__ __align__(16) __half g_Mfh[Nn*Nn];
__device__ float    g_h1t[Nn*Dd], g_h1s[Nn*Dd], g_h2t[Nn*Dd], g_h2s[Nn*Dd];
__device__ __align__(16) __half g_h1th[Nn*Dd], g_h1sh[Nn*Dd];
__device__ float    g_fgt[Nn*Dd], g_fgs[Nn*Dd];
__device__ __align__(16) __half g_fgth[Nn*Dd], g_fgsh[Nn*Dd];
__device__ float    g_pp1[2*8*Nn*Dd];     // distinct regions: L1 non-coherence across stages
__device__ float    g_pp2[2*8*Nn*Dd];
__device__ float    g_pp3[2*4*Kp*Dd];
__device__ float    g_rowp1[32*Nn], g_colp1[32*Nn];
__device__ float    g_pos1[Nn];
__device__ float    g_scores[Nn];
__device__ int      g_selidx[Kp];
__device__ float    g_nht[Kp*Dd], g_nhs[Kp*Dd];
__device__ __align__(16) __half g_nhth[Kp*Dd], g_nhsh[Kp*Dd];
__device__ unsigned g_Pbits[Kp*32];
__device__ float    g_dinvp[Kp];
__device__ __align__(16) __half g_Pfh[Kp*Kp];
__device__ float    g_ph1t[Kp*Dd], g_ph1s[Kp*Dd];
__device__ float    g_fpt[Kp*Dd], g_fps[Kp*Dd];
__device__ __align__(16) __half g_fpth[Kp*Dd], g_fpsh[Kp*Dd];
__device__ float    g_rowp2[16*Kp], g_colp2[16*Kp];
__device__ float    g_pos2[Kp];
__device__ float    g_fin1[NB], g_fin2[NB];
__device__ unsigned g_barcnt;
__device__ volatile unsigned g_bargen;

union H8 { uint4 u; __half2 h[4]; };

__device__ __forceinline__ void gridbar() {
    __syncthreads();
    if (threadIdx.x == 0) {
        unsigned gen = g_bargen;
        __threadfence();
        if (atomicAdd(&g_barcnt, 1u) == gridDim.x - 1) {
            g_barcnt = 0;
            __threadfence();
            g_bargen = gen + 1;
        } else {
            while (g_bargen == gen) { }
        }
    }
    __syncthreads();
}

__device__ __forceinline__ void cp16(uint32_t dst, const void* src) {
    asm volatile("cp.async.cg.shared.global [%0], [%1], 16;" :: "r"(dst), "l"(src));
}
__device__ __forceinline__ void cp_commit() { asm volatile("cp.async.commit_group;"); }
template <int N> __device__ __forceinline__ void cp_wait() {
    asm volatile("cp.async.wait_group %0;" :: "n"(N));
}

// Fast exp on ALU pipes (arg in [-29, 0.1]).
__device__ __forceinline__ float fexp(float x) {
    float y = x * 1.4426950408889634f;
    float n = floorf(y);
    float f = y - n;
    float p = 1.3333558146e-3f;
    p = p * f + 9.6181291076e-3f;
    p = p * f + 5.5504108665e-2f;
    p = p * f + 2.4022650696e-1f;
    p = p * f + 6.9314718056e-1f;
    p = p * f + 1.0f;
    return p * __int_as_float(((int)n + 127) << 23);
}

// ----------------- stage tile functions -----------------

// embed/lin shared GEMM-row tile: 16 rows, K-chunks of 64; 256 thr (compute on tid<128).
__device__ void linlike_tile(char* sm, int R0,
                             const float* X0, const float* X1, const float* X2,
                             int nparts, int ldx0,
                             const float* W, const float* b,
                             float* OUT, __half* OUTH,
                             const float* Wp, const float* bp, int do_score) {
    float (*srow)[64] = (float(*)[64])sm;
    float (*sW)[Dd]   = (float(*)[Dd])(sm + 4096);
    float (*sred)[132]= (float(*)[132])(sm + 36864);
    float* sscale     = (float*)(sm + 45312);
    const float* Xs[3] = { X0, X1, X2 };
    int tid = threadIdx.x;
    float acc[16];
#pragma unroll
    for (int r = 0; r < 16; r++) acc[r] = 0.f;
    int K = nparts * 64;           // in units of 64-col chunks count below
    for (int kc = 0; kc < K * 1; kc++) ;  // (placeholder removed)
    int Ktot = nparts * ((ldx0 == Cc) ? Cc : Dd);
    for (int kc = 0; kc < Ktot; kc += 64) {
        const float* Xp; int off; int ld;
        if (ldx0 == Cc) { Xp = X0; off = kc; ld = Cc; }
        else            { Xp = Xs[kc >> 7]; off = kc & 127; ld = Dd; }
        __syncthreads();
        {   // srow: 256 float4 tasks
            int r = tid >> 4, kq = tid & 15;
            ((float4*)srow[r])[kq] = *(const float4*)&Xp[(size_t)(R0 + r) * ld + off + kq*4];
        }
        for (int u = tid; u < 2048; u += NT) {   // sW: 2048 float4 tasks
            int k = u >> 5, q = u & 31;
            ((float4*)sW[k])[q] = *(const float4*)&W[(size_t)(kc + k) * Dd + q*4];
        }
        __syncthreads();
        if (tid < 128) {
            int d = tid;
#pragma unroll 4
            for (int k4 = 0; k4 < 16; k4++) {
                float w0 = sW[k4*4+0][d], w1 = sW[k4*4+1][d], w2 = sW[k4*4+2][d], w3 = sW[k4*4+3][d];
#pragma unroll
                for (int r = 0; r < 16; r++) {
                    float4 s4 = ((float4*)srow[r])[k4];
                    acc[r] += s4.x*w0; acc[r] += s4.y*w1; acc[r] += s4.z*w2; acc[r] += s4.w*w3;
                }
            }
        }
    }
    __syncthreads();
    if (tid < 128) {
        float bb = b[tid];
#pragma unroll
        for (int r = 0; r < 16; r++) sred[r][tid] = acc[r] + bb;
    }
    __syncthreads();
    if (tid < 128) {
        int lane = tid & 31, w = tid >> 5;
        float wp0 = 0.f, wp1 = 0.f, wp2 = 0.f, wp3 = 0.f;
        if (do_score) { wp0 = Wp[lane]; wp1 = Wp[lane+32]; wp2 = Wp[lane+64]; wp3 = Wp[lane+96]; }
#pragma unroll
        for (int m = 0; m < 4; m++) {
            int r = w*4 + m;
            float x0 = sred[r][lane], x1 = sred[r][lane+32], x2 = sred[r][lane+64], x3 = sred[r][lane+96];
            float s = x0*x0 + x1*x1 + x2*x2 + x3*x3;
            float sp = x0*wp0 + x1*wp1 + x2*wp2 + x3*wp3;
#pragma unroll
            for (int o = 16; o; o >>= 1) { s += __shfl_xor_sync(0xffffffffu, s, o);
                                           sp += __shfl_xor_sync(0xffffffffu, sp, o); }
            if (lane == 0) {
                float scale = rsqrtf(s);
                sscale[r] = scale;
                if (do_score) g_scores[R0 + r] = 1.f / (1.f + expf(-(sp * scale + bp[0])));
            }
        }
    }
    __syncthreads();
    if (tid < 128) {
#pragma unroll
        for (int r = 0; r < 16; r++) {
            float v = sred[r][tid] * sscale[r];
            OUT[(size_t)(R0 + r) * Dd + tid] = v;
            OUTH[(size_t)(R0 + r) * Dd + tid] = __float2half_rn(v);
        }
    }
    __syncthreads();
}

// gramA lower-triangle tile (64x64), bitmask output. 256 thr.
__device__ void gramA_tile(char* sm, int l) {
    float* sx = (float*)sm;                       // 64*68
    float* sy = (float*)(sm + 17408);             // 64*68
    unsigned (*sbits)[2] = (unsigned(*)[2])(sm + 34816);
    unsigned (*tbits)[2] = (unsigned(*)[2])(sm + 35328);
    int by = (int)((sqrtf(8.f * l + 1.f) - 1.f) * 0.5f);
    while ((by + 1) * (by + 2) / 2 <= l) by++;
    while (by * (by + 1) / 2 > l) by--;
    int bx = l - by * (by + 1) / 2;
    int I0 = by * 64, J0 = bx * 64;
    int t = threadIdx.x, tx = t & 15, ty = t >> 4;
    float acc[4][4];
#pragma unroll
    for (int a = 0; a < 4; a++)
#pragma unroll
        for (int c = 0; c < 4; c++) acc[a][c] = 0.f;
    for (int kc = 0; kc < Dd; kc += 64) {
        __syncthreads();
        for (int u = t; u < 4096; u += NT) { int k = u & 63, r = u >> 6;
            sx[k*68 + r] = g_fet[(size_t)(I0 + r) * Dd + kc + k];
            sy[k*68 + r] = g_fet[(size_t)(J0 + r) * Dd + kc + k]; }
        __syncthreads();
#pragma unroll 8
        for (int k = 0; k < 64; k++) {
            float4 a4 = *(const float4*)&sx[k*68 + ty*4];
            float4 b4 = *(const float4*)&sy[k*68 + tx*4];
            acc[0][0] += a4.x*b4.x; acc[0][1] += a4.x*b4.y; acc[0][2] += a4.x*b4.z; acc[0][3] += a4.x*b4.w;
            acc[1][0] += a4.y*b4.x; acc[1][1] += a4.y*b4.y; acc[1][2] += a4.y*b4.z; acc[1][3] += a4.y*b4.w;
            acc[2][0] += a4.z*b4.x; acc[2][1] += a4.z*b4.y; acc[2][2] += a4.z*b4.z; acc[2][3] += a4.z*b4.w;
            acc[3][0] += a4.w*b4.x; acc[3][1] += a4.w*b4.y; acc[3][2] += a4.w*b4.z; acc[3][3] += a4.w*b4.w;
        }
    }
    __syncthreads();
    if (t < 128) { ((unsigned*)sbits)[t] = 0; ((unsigned*)tbits)[t] = 0; }
    __syncthreads();
    int wj = (tx * 4) >> 5, shj = (tx * 4) & 31;
    int wi = (ty * 4) >> 5, shi = (ty * 4) & 31;
#pragma unroll
    for (int rr = 0; rr < 4; rr++) {
        int i = I0 + ty*4 + rr;
        unsigned nib = 0;
#pragma unroll
        for (int cc = 0; cc < 4; cc++) {
            int j = J0 + tx*4 + cc;
            if (acc[rr][cc] > 0.f || i == j) nib |= 1u << cc;
        }
        if (nib) atomicOr(&sbits[ty*4 + rr][wj], nib << shj);
    }
#pragma unroll
    for (int cc = 0; cc < 4; cc++) {
        int j = J0 + tx*4 + cc;
        unsigned nib = 0;
#pragma unroll
        for (int rr = 0; rr < 4; rr++) {
            int i = I0 + ty*4 + rr;
            if (acc[rr][cc] > 0.f || i == j) nib |= 1u << rr;
        }
        if (nib) atomicOr(&tbits[tx*4 + cc][wi], nib << shi);
    }
    __syncthreads();
    if (t < 128) {
        int il = t >> 1, ww = t & 1;
        g_Abits[(size_t)(I0 + il) * 64 + (J0 >> 5) + ww] = sbits[il][ww];
        g_Abits[(size_t)(J0 + il) * 64 + (I0 >> 5) + ww] = tbits[il][ww];
    }
    __syncthreads();
}

// prop tile: 128 i-rows x 128 d via fp16 wmma, cp.async double-buffered.
__device__ void prop_tile(char* sm, int tile, const __half* Mf,
                          const __half* Hth, const __half* Hsh,
                          float* pp, int n, int ns) {
    __half (*As)[128 * APADH] = (__half(*)[128 * APADH])sm;
    __half (*Bs)[32 * BPADH]  = (__half(*)[32 * BPADH])(sm + 20480);
    int nx = n >> 7;
    int y = tile / nx, x = tile - y * nx;
    int ts = y / ns, split = y - ts * ns;
    const __half* H = ts ? Hsh : Hth;
    int i0 = x * 128;
    int chunk = n / ns, jb = split * chunk;
    int tid = threadIdx.x;
    int warp = tid >> 5, wm = warp & 3, wn = warp >> 2;
    int ar = tid >> 1, ag = tid & 1;
    int br = tid >> 4, bg = tid & 15;
    wmma::fragment<wmma::accumulator, 16, 16, 16, float> c[2][4];
#pragma unroll
    for (int mi = 0; mi < 2; mi++)
#pragma unroll
        for (int ni = 0; ni < 4; ni++) wmma::fill_fragment(c[mi][ni], 0.f);
    wmma::fragment<wmma::matrix_a, 16, 16, 16, __half, wmma::row_major> af[2];
    wmma::fragment<wmma::matrix_b, 16, 16, 16, __half, wmma::row_major> bf[4];
    int niter = chunk >> 5;
    auto stage = [&](int buf, int j0) {
        uint32_t abase = (uint32_t)__cvta_generic_to_shared(&As[buf][0]);
        uint32_t bbase = (uint32_t)__cvta_generic_to_shared(&Bs[buf][0]);
#pragma unroll
        for (int g = 0; g < 2; g++)
            cp16(abase + (ar * APADH + (ag*2+g) * 8) * 2,
                 &Mf[(size_t)(i0 + ar) * n + j0 + (ag*2+g) * 8]);
#pragma unroll
        for (int p = 0; p < 2; p++)
            cp16(bbase + ((br + p*16) * BPADH + bg * 8) * 2,
                 &H[(size_t)(j0 + br + p*16) * Dd + bg * 8]);
    };
    __syncthreads();
    stage(0, jb);
    cp_commit();
    for (int it = 0; it < niter; it++) {
        int cur = it & 1;
        if (it + 1 < niter) { stage(cur ^ 1, jb + (it + 1) * 32); cp_commit(); cp_wait<1>(); }
        else cp_wait<0>();
        __syncthreads();
#pragma unroll
        for (int kk = 0; kk < 2; kk++) {
#pragma unroll
            for (int mi = 0; mi < 2; mi++)
                wmma::load_matrix_sync(af[mi], &As[cur][(wm*32 + mi*16) * APADH + kk*16], APADH);
#pragma unroll
            for (int ni = 0; ni < 4; ni++)
                wmma::load_matrix_sync(bf[ni], &Bs[cur][(kk*16) * BPADH + wn*64 + ni*16], BPADH);
#pragma unroll
            for (int mi = 0; mi < 2; mi++)
#pragma unroll
                for (int ni = 0; ni < 4; ni++)
                    wmma::mma_sync(c[mi][ni], af[mi], bf[ni], c[mi][ni]);
        }
        __syncthreads();
    }
    float* out = pp + (size_t)(ts * ns + split) * n * Dd;
#pragma unroll
    for (int mi = 0; mi < 2; mi++)
#pragma unroll
        for (int ni = 0; ni < 4; ni++)
            wmma::store_matrix_sync(out + (size_t)(i0 + wm*32 + mi*16) * Dd + wn*64 + ni*16,
                                    c[mi][ni], Dd, wmma::mem_row_major);
    __syncthreads();
}

// combine: O = sum_k partial_k (+optional fp16 mirror), strided over all elements.
__device__ void combine_all(const float* pp, float* Ot, float* Os,
                            __half* Oth, __half* Osh, int n, int ns) {
    int per = n * 32;   // float4 tasks per ts
    for (int u = blockIdx.x * NT + threadIdx.x; u < per * 2; u += NB * NT) {
        int ts = u >= per;
        int idx = ts ? u - per : u;
        float* O = ts ? Os : Ot;
        __half* OH = ts ? Osh : Oth;
        float4 s = make_float4(0.f, 0.f, 0.f, 0.f);
        for (int k = 0; k < ns; k++) {
            float4 v = *(const float4*)&pp[(size_t)(ts * ns + k) * n * Dd + (size_t)idx * 4];
            s.x += v.x; s.y += v.y; s.z += v.z; s.w += v.w;
        }
        *(float4*)&O[(size_t)idx * 4] = s;
        if (OH) {
            *(__half2*)&OH[(size_t)idx * 4] = __floats2half2_rn(s.x, s.y);
            *(__half2*)&OH[(size_t)idx * 4 + 2] = __floats2half2_rn(s.z, s.w);
        }
    }
}

// gramnce tile (64x64) via fp16 wmma; Gs aliases sx. 256 thr.
__device__ void gramnce_tile(char* sm, int tile,
                             const __half* Xh, const __half* Yh,
                             float* rowp, float* colp, float* pos, int n) {
    __half* sx = (__half*)sm;
    __half* sy = (__half*)(sm + 17408);
    float (*cbuf)[64] = (float(*)[64])(sm + 34816);
    float* Gs = (float*)sm;
    int nxt = n >> 6;
    int by = tile / nxt, bx = tile - by * nxt;
    int t = threadIdx.x, tx = t & 15, ty = t >> 4;
    int warp = t >> 5, wm = warp & 3, wn = warp >> 2;
    int I0 = by * 64, J0 = bx * 64;
    int r0 = t >> 4, g0 = t & 15;
    __syncthreads();
#pragma unroll
    for (int p = 0; p < 4; p++) {
        int r = r0 + p * 16;
        *(uint4*)&sx[r * GPAD + g0 * 8] = *(const uint4*)&Xh[(size_t)(I0 + r) * Dd + g0 * 8];
        *(uint4*)&sy[r * GPAD + g0 * 8] = *(const uint4*)&Yh[(size_t)(J0 + r) * Dd + g0 * 8];
    }
    __syncthreads();
    wmma::fragment<wmma::accumulator, 16, 16, 16, float> c[2];
    wmma::fill_fragment(c[0], 0.f);
    wmma::fill_fragment(c[1], 0.f);
    wmma::fragment<wmma::matrix_a, 16, 16, 16, __half, wmma::row_major> af;
    wmma::fragment<wmma::matrix_b, 16, 16, 16, __half, wmma::col_major> bf[2];
#pragma unroll
    for (int k = 0; k < 8; k++) {
        wmma::load_matrix_sync(af, &sx[(wm*16) * GPAD + k*16], GPAD);
#pragma unroll
        for (int ni = 0; ni < 2; ni++)
            wmma::load_matrix_sync(bf[ni], &sy[(wn*32 + ni*16) * GPAD + k*16], GPAD);
        wmma::mma_sync(c[0], af, bf[0], c[0]);
        wmma::mma_sync(c[1], af, bf[1], c[1]);
    }
    __syncthreads();
#pragma unroll
    for (int ni = 0; ni < 2; ni++)
        wmma::store_matrix_sync(&Gs[(wm*16) * 68 + wn*32 + ni*16], c[ni], 68, wmma::mem_row_major);
    __syncthreads();
    if (I0 == J0 && t < 64) pos[I0 + t] = Gs[t * 68 + t];
    float e[4][4];
#pragma unroll
    for (int rr = 0; rr < 4; rr++) {
        float rl = 0.f;
#pragma unroll
        for (int cc = 0; cc < 4; cc++) {
            e[rr][cc] = fexp((Gs[(ty*4+rr) * 68 + tx*4 + cc] - 1.f) * TINV);
            rl += e[rr][cc];
        }
#pragma unroll
        for (int o = 8; o; o >>= 1) rl += __shfl_xor_sync(0xffffffffu, rl, o);
        if (tx == 0) rowp[(size_t)bx * n + I0 + ty*4 + rr] = rl;
    }
#pragma unroll
    for (int cc = 0; cc < 4; cc++)
        cbuf[ty][tx*4 + cc] = e[0][cc] + e[1][cc] + e[2][cc] + e[3][cc];
    __syncthreads();
    if (t < 64) {
        float s = 0.f;
#pragma unroll
        for (int y = 0; y < 16; y++) s += cbuf[y][t];
        colp[(size_t)by * n + J0 + t] = s;
    }
    __syncthreads();
}

// subbits tile: 64x64 pooled adjacency via bit-row intersection. 256 thr.
__device__ void subbits_tile(char* sm, int tile) {
    unsigned* pr = (unsigned*)sm;
    unsigned* qr = (unsigned*)(sm + 17408);
    unsigned (*pb)[2] = (unsigned(*)[2])(sm + 34816);
    int by = tile >> 4, bx = tile & 15;
    int t = threadIdx.x;
    int P0 = by * 64, Q0 = bx * 64;
    __syncthreads();
    for (int u = t; u < 1024; u += NT) {
        int r = u >> 4, w4 = u & 15;
        *(uint4*)&pr[r*68 + w4*4] = *(const uint4*)&g_Abits[(size_t)g_selidx[P0 + r] * 64 + w4*4];
        *(uint4*)&qr[r*68 + w4*4] = *(const uint4*)&g_Abits[(size_t)g_selidx[Q0 + r] * 64 + w4*4];
    }
    if (t < 128) ((unsigned*)pb)[t] = 0;
    __syncthreads();
    int p = t >> 2, qb = t & 3;
    unsigned anyv[16];
#pragma unroll
    for (int qq = 0; qq < 16; qq++) anyv[qq] = 0;
    for (int w4 = 0; w4 < 16; w4++) {
        uint4 a = *(const uint4*)&pr[p*68 + w4*4];
#pragma unroll
        for (int qq = 0; qq < 16; qq++) {
            uint4 bv = *(const uint4*)&qr[(qb*16 + qq)*68 + w4*4];
            anyv[qq] |= (a.x & bv.x) | (a.y & bv.y) | (a.z & bv.z) | (a.w & bv.w);
        }
    }
    unsigned res = 0;
#pragma unroll
    for (int qq = 0; qq < 16; qq++) res |= (anyv[qq] ? 1u : 0u) << qq;
    atomicOr(&pb[p][qb >> 1], res << ((qb & 1) * 16));
    __syncthreads();
    if (t < 128) g_Pbits[(size_t)(P0 + (t >> 1)) * 32 + (Q0 >> 5) + (t & 1)] = pb[t >> 1][t & 1];
    __syncthreads();
}

// build Mf strided: Mf[i,j] = bit ? fp16(dinv_i*dinv_j) : 0.
__device__ void build_all(const unsigned* bits, const float* dinv, __half* Mf,
                          int n, int nwords) {
    int n8 = n >> 3;
    for (int idx = blockIdx.x * NT + threadIdx.x; idx < n * n8; idx += NB * NT) {
        int i = idx / n8, g8 = idx - i * n8;
        unsigned word = bits[(size_t)i * nwords + (g8 >> 2)];
        int sh = (g8 & 3) * 8;
        float di = dinv[i];
        float4 a = *(const float4*)&dinv[g8 * 8];
        float4 c = *(const float4*)&dinv[g8 * 8 + 4];
        H8 o;
        o.h[0] = __floats2half2_rn((word >> (sh+0)) & 1 ? di*a.x : 0.f, (word >> (sh+1)) & 1 ? di*a.y : 0.f);
        o.h[1] = __floats2half2_rn((word >> (sh+2)) & 1 ? di*a.z : 0.f, (word >> (sh+3)) & 1 ? di*a.w : 0.f);
        o.h[2] = __floats2half2_rn((word >> (sh+4)) & 1 ? di*c.x : 0.f, (word >> (sh+5)) & 1 ? di*c.y : 0.f);
        o.h[3] = __floats2half2_rn((word >> (sh+6)) & 1 ? di*c.z : 0.f, (word >> (sh+7)) & 1 ? di*c.w : 0.f);
        *(uint4*)&Mf[(size_t)i * n + g8 * 8] = o.u;
    }
}

__device__ void dinv_all(const unsigned* bits, float* dinv, int n, int nwords) {
    for (int i = blockIdx.x * NT + threadIdx.x; i < n; i += NB * NT) {
        const uint4* p = (const uint4*)&bits[(size_t)i * nwords];
        int dg = 0;
        for (int w = 0; w < nwords/4; w++) { uint4 v = p[w];
            dg += __popc(v.x) + __popc(v.y) + __popc(v.z) + __popc(v.w); }
        dinv[i] = rsqrtf((float)dg);
    }
}

// ----------------- mega kernel -----------------

__global__ void __launch_bounds__(NT, 2) mega_kernel(
        const float* __restrict__ fs, const float* __restrict__ ft,
        const float* __restrict__ We, const float* __restrict__ be,
        const float* __restrict__ Wg, const float* __restrict__ bg,
        const float* __restrict__ Wp, const float* __restrict__ bp,
        const float* __restrict__ Wgp, const float* __restrict__ bgp,
        float* __restrict__ out) {
    extern __shared__ char sm[];
    int tid = threadIdx.x;

    // 1. embed: tiles = 128 x-tiles x 2 branches
    for (int tile = blockIdx.x; tile < 256; tile += NB) {
        int branch = tile & 1, xt = tile >> 1;
        linlike_tile(sm, xt * 16,
                     branch ? ft : fs, nullptr, nullptr, 1, Cc, We, be,
                     branch ? g_fet : g_fes, branch ? g_feth : g_fesh,
                     nullptr, nullptr, 0);
    }
    gridbar();
    // 2. gramA
    for (int tile = blockIdx.x; tile < 528; tile += NB) gramA_tile(sm, tile);
    gridbar();
    // 3. dinv
    dinv_all(g_Abits, g_dinv, Nn, 64);
    gridbar();
    // 4. build Mf
    build_all(g_Abits, g_dinv, g_Mfh, Nn, 64);
    gridbar();
    // 5. prop hop1
    for (int tile = blockIdx.x; tile < 256; tile += NB)
        prop_tile(sm, tile, g_Mfh, g_feth, g_fesh, g_pp1, Nn, 8);
    gridbar();
    // 6. combine1 (writes h1 + mirrors)
    combine_all(g_pp1, g_h1t, g_h1s, g_h1th, g_h1sh, Nn, 8);
    gridbar();
    // 7. prop hop2
    for (int tile = blockIdx.x; tile < 256; tile += NB)
        prop_tile(sm, tile, g_Mfh, g_h1th, g_h1sh, g_pp2, Nn, 8);
    gridbar();
    // 8. combine2 (writes h2)
    combine_all(g_pp2, g_h2t, g_h2s, nullptr, nullptr, Nn, 8);
    gridbar();
    // 9. lin big (+ scores on teacher)
    for (int tile = blockIdx.x; tile < 256; tile += NB) {
        int branch = tile & 1, xt = tile >> 1;
        if (branch)
            linlike_tile(sm, xt * 16, g_fes, g_h1s, g_h2s, 3, Dd, Wg, bg,
                         g_fgs, g_fgsh, nullptr, nullptr, 0);
        else
            linlike_tile(sm, xt * 16, g_fet, g_h1t, g_h2t, 3, Dd, Wg, bg,
                         g_fgt, g_fgth, Wp, bp, 1);
    }
    gridbar();
    // 10. gramnce big
    for (int tile = blockIdx.x; tile < 1024; tile += NB)
        gramnce_tile(sm, tile, g_fgth, g_fgsh, g_rowp1, g_colp1, g_pos1, Nn);
    gridbar();
    // 11. rank + gather (warp per node)
    {
        int warp = tid >> 5, lane = tid & 31;
        for (int i = blockIdx.x * 8 + warp; i < Nn; i += NB * 8) {
            float si = g_scores[i];
            int c = 0;
            for (int j = lane; j < Nn; j += 32) {
                float sj = g_scores[j];
                c += (sj > si) || (sj == si && j < i);
            }
#pragma unroll
            for (int o = 16; o; o >>= 1) c += __shfl_xor_sync(0xffffffffu, c, o);
            if (c < Kp) {
                if (lane == 0) g_selidx[c] = i;
#pragma unroll
                for (int k = 0; k < 4; k++) {
                    int d = lane + k * 32;
                    float a = g_fgt[(size_t)i * Dd + d] * si;
                    float b = g_fgs[(size_t)i * Dd + d] * si;
                    g_nht[(size_t)c * Dd + d] = a;
                    g_nhs[(size_t)c * Dd + d] = b;
                    g_nhth[(size_t)c * Dd + d] = __float2half_rn(a);
                    g_nhsh[(size_t)c * Dd + d] = __float2half_rn(b);
                }
            }
        }
    }
    gridbar();
    // 12. subbits
    for (int tile = blockIdx.x; tile < 256; tile += NB) subbits_tile(sm, tile);
    gridbar();
    // 13. dinvp
    dinv_all(g_Pbits, g_dinvp, Kp, 32);
    gridbar();
    // 14. build Pf
    build_all(g_Pbits, g_dinvp, g_Pfh, Kp, 32);
    gridbar();
    // 15. prop pooled
    for (int tile = blockIdx.x; tile < 64; tile += NB)
        prop_tile(sm, tile, g_Pfh, g_nhth, g_nhsh, g_pp3, Kp, 4);
    gridbar();
    // 16. combine pooled
    combine_all(g_pp3, g_ph1t, g_ph1s, nullptr, nullptr, Kp, 4);
    gridbar();
    // 17. lin pooled
    for (int tile = blockIdx.x; tile < 128; tile += NB) {
        int branch = tile & 1, xt = tile >> 1;
        if (branch)
            linlike_tile(sm, xt * 16, g_nhs, g_ph1s, nullptr, 2, Dd, Wgp, bgp,
                         g_fps, g_fpsh, nullptr, nullptr, 0);
        else
            linlike_tile(sm, xt * 16, g_nht, g_ph1t, nullptr, 2, Dd, Wgp, bgp,
                         g_fpt, g_fpth, nullptr, nullptr, 0);
    }
    gridbar();
    // 18. gramnce pooled
    for (int tile = blockIdx.x; tile < 256; tile += NB)
        gramnce_tile(sm, tile, g_fpth, g_fpsh, g_rowp2, g_colp2, g_pos2, Kp);
    gridbar();
    // 19. final partials
    {
        float* red = (float*)sm;
        float s1 = 0.f, s2 = 0.f;
        for (int i = blockIdx.x * NT + tid; i < Nn; i += NB * NT) {
            float rs = 0.f, cs = 0.f;
            for (int k = 0; k < 32; k++) { rs += g_rowp1[(size_t)k * Nn + i]; cs += g_colp1[(size_t)k * Nn + i]; }
            s1 += __logf(rs) + __logf(cs) + 2.f * (1.f - g_pos1[i]) * TINV;
        }
        for (int i = blockIdx.x * NT + tid; i < Kp; i += NB * NT) {
            float rs = 0.f, cs = 0.f;
            for (int k = 0; k < 16; k++) { rs += g_rowp2[(size_t)k * Kp + i]; cs += g_colp2[(size_t)k * Kp + i]; }
            s2 += __logf(rs) + __logf(cs) + 2.f * (1.f - g_pos2[i]) * TINV;
        }
        __syncthreads();
        red[tid] = s1; __syncthreads();
        for (int s = 128; s; s >>= 1) { if (tid < s) red[tid] += red[tid + s]; __syncthreads(); }
        if (tid == 0) g_fin1[blockIdx.x] = red[0];
        __syncthreads();
        red[tid] = s2; __syncthreads();
        for (int s = 128; s; s >>= 1) { if (tid < s) red[tid] += red[tid + s]; __syncthreads(); }
        if (tid == 0) g_fin2[blockIdx.x] = red[0];
    }
    gridbar();
    // 20. block 0 reduces partials
    if (blockIdx.x == 0) {
        float* red = (float*)sm;
        float s1 = 0.f, s2 = 0.f;
        for (int u = tid; u < NB; u += NT) { s1 += g_fin1[u]; s2 += g_fin2[u]; }
        red[tid] = s1; __syncthreads();
        for (int s = 128; s; s >>= 1) { if (tid < s) red[tid] += red[tid + s]; __syncthreads(); }
        s1 = red[0]; __syncthreads();
        red[tid] = s2; __syncthreads();
        for (int s = 128; s; s >>= 1) { if (tid < s) red[tid] += red[tid + s]; __syncthreads(); }
        if (tid == 0) out[0] = s1 / (float)Nn + red[0] / (float)Kp;
    }
}

// ----------------- launch -----------------

extern "C" void kernel_launch(void* const* d_in, const int* in_sizes, int n_in,
                              void* d_out, int out_size) {
    const float* fs  = (const float*)d_in[0];
    const float* ft  = (const float*)d_in[1];
    const float* We  = (const float*)d_in[2];
    const float* be  = (const float*)d_in[3];
    const float* Wg  = (const float*)d_in[4];
    const float* bg  = (const float*)d_in[5];
    const float* Wp  = (const float*)d_in[6];
    const float* bp  = (const float*)d_in[7];
    const float* Wgp = (const float*)d_in[8];
    const float* bgp = (const float*)d_in[9];
    float* out = (float*)d_out;
    mega_kernel<<<NB, NT, SMEM_BYTES>>>(fs, ft, We, be, Wg, bg, Wp, bp, Wgp, bgp, out);
}